// round 3
// baseline (speedup 1.0000x reference)
#include <cuda_runtime.h>
#include <cuda_bf16.h>
#include <math.h>

// Problem constants
#define S 128
#define B 32
#define E 300
#define H 200
#define G 800      // 4*H
#define NT 1600    // 2 dirs * G
#define MROWS 4096 // S*B
#define T 17

// Scratch (device globals; no allocation allowed). Kernels reference these
// directly — no cudaGetSymbolAddress in the launch path.
__device__ float g_Wt0[300 * NT];          // W0^T  [k][d*800+g]
__device__ float g_Wt1[400 * NT];          // W1^T
__device__ float g_UT0[2 * 50 * G * 4];    // U0 repacked [d][k/4][g][4]
__device__ float g_UT1[2 * 50 * G * 4];
__device__ float g_GI0[MROWS * NT];        // gate inputs layer0 [s][b][d*800+g]
__device__ float g_GI1[MROWS * NT];
__device__ float g_H0[MROWS * 400];        // layer0 output [s][b][400]
__device__ float g_H1[MROWS * 400];

__device__ __forceinline__ float sigf(float x) { return 1.0f / (1.0f + expf(-x)); }

// ---------------------------------------------------------------------------
// Transpose W ([2][800][K] -> [K][1600]) into g_Wt0 or g_Wt1 (sel)
// ---------------------------------------------------------------------------
__global__ void transpose_W(const float* __restrict__ W, int K, int sel) {
    float* Wt = sel ? g_Wt1 : g_Wt0;
    int idx = blockIdx.x * 256 + threadIdx.x;
    int total = NT * K;
    if (idx < total) {
        int n = idx / K, k = idx - n * K;
        Wt[k * NT + n] = W[idx];
    }
}

// ---------------------------------------------------------------------------
// Repack U ([2][800][200] -> [d][k/4][g][4])
// ---------------------------------------------------------------------------
__global__ void repack_U(const float* __restrict__ U, int sel) {
    float* UT4 = sel ? g_UT1 : g_UT0;
    int idx = blockIdx.x * 256 + threadIdx.x;
    const int total = 2 * G * H;
    if (idx < total) {
        int d = idx / (G * H);
        int rem = idx - d * (G * H);
        int g = rem / H;
        int k = rem - g * H;
        UT4[(((d * 50 + (k >> 2)) * G) + g) * 4 + (k & 3)] = U[idx];
    }
}

// ---------------------------------------------------------------------------
// Tiled fp32 GEMM: C[m][n] = sum_k A[m][k]*Bm[k][n] + bias[n]
// layer==0: A row m gathered from emb[words[b*S+s]] (m = s*B+b), Bm=g_Wt0, C=g_GI0
// layer==1: A = g_H0, Bm = g_Wt1, C = g_GI1
// Grid: (N/64, M/64), 256 threads, 4x4 micro-tile, BK=16.
// ---------------------------------------------------------------------------
__global__ void gemm64(const float* __restrict__ bias, int K, int layer,
                       const int* __restrict__ words, const float* __restrict__ emb) {
    const float* A  = layer ? g_H0 : nullptr;
    const float* Bm = layer ? g_Wt1 : g_Wt0;
    float* C        = layer ? g_GI1 : g_GI0;
    __shared__ float As[16][64];
    __shared__ float Bs[16][64];
    const int tid = threadIdx.x;
    const int m0 = blockIdx.y * 64, n0 = blockIdx.x * 64;
    const int tx = tid & 15, ty = tid >> 4;
    float acc[4][4] = {};

    for (int k0 = 0; k0 < K; k0 += 16) {
        // load A tile (64 rows x 16 cols)
#pragma unroll
        for (int i = 0; i < 4; i++) {
            int idx = tid + i * 256;
            int r = idx >> 4, c = idx & 15;
            int m = m0 + r, kk = k0 + c;
            float v = 0.0f;
            if (kk < K) {
                if (layer == 0) {
                    int s = m >> 5, b = m & 31;
                    int w = words[b * S + s];
                    v = emb[w * E + kk];
                } else {
                    v = A[m * K + kk];
                }
            }
            As[c][r] = v;
        }
        // load B tile (16 rows x 64 cols)
#pragma unroll
        for (int i = 0; i < 4; i++) {
            int idx = tid + i * 256;
            int r = idx >> 6, c = idx & 63;
            int kk = k0 + r;
            Bs[r][c] = (kk < K) ? Bm[kk * NT + n0 + c] : 0.0f;
        }
        __syncthreads();
#pragma unroll
        for (int kk = 0; kk < 16; kk++) {
            float4 av = *(const float4*)&As[kk][ty * 4];
            float4 bv = *(const float4*)&Bs[kk][tx * 4];
            float a[4] = {av.x, av.y, av.z, av.w};
            float b[4] = {bv.x, bv.y, bv.z, bv.w};
#pragma unroll
            for (int i = 0; i < 4; i++)
#pragma unroll
                for (int j = 0; j < 4; j++)
                    acc[i][j] = fmaf(a[i], b[j], acc[i][j]);
        }
        __syncthreads();
    }
#pragma unroll
    for (int i = 0; i < 4; i++) {
        int m = m0 + ty * 4 + i;
#pragma unroll
        for (int j = 0; j < 4; j++) {
            int n = n0 + tx * 4 + j;
            C[m * NT + n] = acc[i][j] + bias[n];
        }
    }
}

// ---------------------------------------------------------------------------
// LSTM recurrence. Block = (pair of batches, direction). Threads 0..199 each
// own one hidden unit (c in register). h in SMEM, U via LDG.128 (repacked).
// GI: [s][b][1600] (d*800 + gate*200 + j). H out: [s][b][400] (d*200 + j).
// layer selects g_GI0/g_UT0/g_H0 vs g_GI1/g_UT1/g_H1.
// ---------------------------------------------------------------------------
__global__ void lstm_rec(int layer) {
    const float* GI   = layer ? g_GI1 : g_GI0;
    const float* UT4  = layer ? g_UT1 : g_UT0;
    float* Hout       = layer ? g_H1  : g_H0;
    const int bp = blockIdx.x;   // 0..15
    const int d = blockIdx.y;    // 0,1
    const int tid = threadIdx.x; // 0..255
    __shared__ float h0s[200];
    __shared__ float h1s[200];
    float c0 = 0.0f, c1 = 0.0f;
    if (tid < 200) { h0s[tid] = 0.0f; h1s[tid] = 0.0f; }
    __syncthreads();
    const float* UTd = UT4 + d * 50 * (G * 4);
    const int b0 = bp * 2, b1 = bp * 2 + 1;

    float ai0, af0, ag0, ao0, ai1, af1, ag1, ao1;
    for (int step = 0; step < 128; step++) {
        const int t = d ? (127 - step) : step;
        if (tid < 200) {
            const float* gi0 = GI + (t * B + b0) * NT + d * 800;
            const float* gi1 = gi0 + NT;
            ai0 = gi0[tid];       af0 = gi0[200 + tid];
            ag0 = gi0[400 + tid]; ao0 = gi0[600 + tid];
            ai1 = gi1[tid];       af1 = gi1[200 + tid];
            ag1 = gi1[400 + tid]; ao1 = gi1[600 + tid];
#pragma unroll 2
            for (int kq = 0; kq < 50; kq++) {
                const float4* u = (const float4*)(UTd + kq * (G * 4));
                float4 ui = u[tid];
                float4 uf = u[200 + tid];
                float4 ug = u[400 + tid];
                float4 uo = u[600 + tid];
                float4 h0 = *(const float4*)&h0s[kq * 4];
                float4 h1 = *(const float4*)&h1s[kq * 4];
                ai0 = fmaf(h0.x, ui.x, ai0); ai0 = fmaf(h0.y, ui.y, ai0);
                ai0 = fmaf(h0.z, ui.z, ai0); ai0 = fmaf(h0.w, ui.w, ai0);
                af0 = fmaf(h0.x, uf.x, af0); af0 = fmaf(h0.y, uf.y, af0);
                af0 = fmaf(h0.z, uf.z, af0); af0 = fmaf(h0.w, uf.w, af0);
                ag0 = fmaf(h0.x, ug.x, ag0); ag0 = fmaf(h0.y, ug.y, ag0);
                ag0 = fmaf(h0.z, ug.z, ag0); ag0 = fmaf(h0.w, ug.w, ag0);
                ao0 = fmaf(h0.x, uo.x, ao0); ao0 = fmaf(h0.y, uo.y, ao0);
                ao0 = fmaf(h0.z, uo.z, ao0); ao0 = fmaf(h0.w, uo.w, ao0);
                ai1 = fmaf(h1.x, ui.x, ai1); ai1 = fmaf(h1.y, ui.y, ai1);
                ai1 = fmaf(h1.z, ui.z, ai1); ai1 = fmaf(h1.w, ui.w, ai1);
                af1 = fmaf(h1.x, uf.x, af1); af1 = fmaf(h1.y, uf.y, af1);
                af1 = fmaf(h1.z, uf.z, af1); af1 = fmaf(h1.w, uf.w, af1);
                ag1 = fmaf(h1.x, ug.x, ag1); ag1 = fmaf(h1.y, ug.y, ag1);
                ag1 = fmaf(h1.z, ug.z, ag1); ag1 = fmaf(h1.w, ug.w, ag1);
                ao1 = fmaf(h1.x, uo.x, ao1); ao1 = fmaf(h1.y, uo.y, ao1);
                ao1 = fmaf(h1.z, uo.z, ao1); ao1 = fmaf(h1.w, uo.w, ao1);
            }
        }
        __syncthreads(); // all reads of old h done
        if (tid < 200) {
            float cn0 = sigf(af0) * c0 + sigf(ai0) * tanhf(ag0);
            c0 = cn0;
            float hn0 = sigf(ao0) * tanhf(cn0);
            float cn1 = sigf(af1) * c1 + sigf(ai1) * tanhf(ag1);
            c1 = cn1;
            float hn1 = sigf(ao1) * tanhf(cn1);
            h0s[tid] = hn0;
            h1s[tid] = hn1;
            Hout[(t * B + b0) * 400 + d * 200 + tid] = hn0;
            Hout[(t * B + b1) * 400 + d * 200 + tid] = hn1;
        }
        __syncthreads();
    }
}

// ---------------------------------------------------------------------------
// Output projection: out[b][s][t] = sigmoid(g_H1[s][b][:400] . out_w[t] + out_b[t])
// One block per (s,b). 17 outputs x 8 threads each, shfl-reduce width 8.
// ---------------------------------------------------------------------------
__global__ void out_proj(const float* __restrict__ ow,
                         const float* __restrict__ ob, float* __restrict__ out) {
    __shared__ float x[400];
    const int m = blockIdx.x; // s*B + b
    const int tid = threadIdx.x;
    for (int i = tid; i < 400; i += blockDim.x) x[i] = g_H1[m * 400 + i];
    __syncthreads();
    if (tid < 136) {
        const int tt = tid >> 3, l = tid & 7;
        float acc = 0.0f;
        for (int k = l; k < 400; k += 8) acc = fmaf(x[k], ow[tt * 400 + k], acc);
        unsigned mask = (tid < 128) ? 0xffffffffu : 0xffu;
        acc += __shfl_down_sync(mask, acc, 4, 8);
        acc += __shfl_down_sync(mask, acc, 2, 8);
        acc += __shfl_down_sync(mask, acc, 1, 8);
        if (l == 0) {
            int s = m >> 5, b = m & 31;
            out[(b * S + s) * T + tt] = sigf(acc + ob[tt]);
        }
    }
}

// ---------------------------------------------------------------------------
extern "C" void kernel_launch(void* const* d_in, const int* in_sizes, int n_in,
                              void* d_out, int out_size) {
    const int* words = (const int*)d_in[0];
    const float* emb = (const float*)d_in[3];
    const float* Wih0 = (const float*)d_in[7];
    const float* Whh0 = (const float*)d_in[8];
    const float* b0 = (const float*)d_in[9];
    const float* Wih1 = (const float*)d_in[10];
    const float* Whh1 = (const float*)d_in[11];
    const float* b1 = (const float*)d_in[12];
    const float* ow = (const float*)d_in[13];
    const float* ob = (const float*)d_in[14];
    float* out = (float*)d_out;

    // weight reshapes (cheap, parallel)
    transpose_W<<<(NT * 300 + 255) / 256, 256>>>(Wih0, 300, 0);
    transpose_W<<<(NT * 400 + 255) / 256, 256>>>(Wih1, 400, 1);
    repack_U<<<(2 * G * H + 255) / 256, 256>>>(Whh0, 0);
    repack_U<<<(2 * G * H + 255) / 256, 256>>>(Whh1, 1);

    // layer 0 input projection (fused embedding gather)
    gemm64<<<dim3(NT / 64, MROWS / 64), 256>>>(b0, 300, 0, words, emb);
    // layer 0 recurrence
    lstm_rec<<<dim3(16, 2), 256>>>(0);
    // layer 1 input projection
    gemm64<<<dim3(NT / 64, MROWS / 64), 256>>>(b1, 400, 1, nullptr, nullptr);
    // layer 1 recurrence
    lstm_rec<<<dim3(16, 2), 256>>>(1);
    // output projection
    out_proj<<<MROWS, 160>>>(ow, ob, out);
}

// round 4
// speedup vs baseline: 1.0187x; 1.0187x over previous
#include <cuda_runtime.h>
#include <cuda_bf16.h>
#include <math.h>

// Problem constants
#define S 128
#define B 32
#define E 300
#define H 200
#define G 800      // 4*H
#define NT 1600    // 2 dirs * G
#define MROWS 4096 // S*B
#define T 17

// Scratch (device globals; no allocation allowed)
__device__ float g_Wt0[300 * NT];          // W0^T  [k][d*800+g]
__device__ float g_Wt1[400 * NT];          // W1^T
__device__ float g_UT0[2 * 50 * G * 4];    // U0 repacked [d][k/4][g][4]
__device__ float g_UT1[2 * 50 * G * 4];
__device__ float g_X0[MROWS * E];          // gathered embeddings [s*B+b][300]
__device__ float g_GI0[MROWS * NT];        // gate inputs layer0 [s][b][d*800+g]
__device__ float g_GI1[MROWS * NT];
__device__ float g_H0[MROWS * 400];        // layer0 output [s][b][400]
__device__ float g_H1[MROWS * 400];

__device__ __forceinline__ float sigf(float x) { return 1.0f / (1.0f + expf(-x)); }

// ---------------------------------------------------------------------------
// Fused prep: blockIdx.y selects task.
//  0: Wih0 [2][800][300] -> g_Wt0 [300][1600]
//  1: Wih1 [2][800][400] -> g_Wt1 [400][1600]
//  2: Whh0 -> g_UT0 [d][k/4][g][4]
//  3: Whh1 -> g_UT1
//  4: embedding gather -> g_X0 (float4 granularity)
// ---------------------------------------------------------------------------
__global__ void prep(const float* __restrict__ Wih0, const float* __restrict__ Wih1,
                     const float* __restrict__ Whh0, const float* __restrict__ Whh1,
                     const int* __restrict__ words, const float* __restrict__ emb) {
    const int task = blockIdx.y;
    const int idx = blockIdx.x * 256 + threadIdx.x;
    if (task == 0) {
        if (idx < NT * 300) {
            int n = idx / 300, k = idx - n * 300;
            g_Wt0[k * NT + n] = Wih0[idx];
        }
    } else if (task == 1) {
        if (idx < NT * 400) {
            int n = idx / 400, k = idx - n * 400;
            g_Wt1[k * NT + n] = Wih1[idx];
        }
    } else if (task == 2) {
        if (idx < 2 * G * H) {
            int d = idx / (G * H);
            int rem = idx - d * (G * H);
            int g = rem / H, k = rem - g * H;
            g_UT0[(((d * 50 + (k >> 2)) * G) + g) * 4 + (k & 3)] = Whh0[idx];
        }
    } else if (task == 3) {
        if (idx < 2 * G * H) {
            int d = idx / (G * H);
            int rem = idx - d * (G * H);
            int g = rem / H, k = rem - g * H;
            g_UT1[(((d * 50 + (k >> 2)) * G) + g) * 4 + (k & 3)] = Whh1[idx];
        }
    } else {
        // X0 gather: 4096 rows x 75 float4 (E=300)
        if (idx < MROWS * 75) {
            int m = idx / 75, c4 = idx - m * 75;
            int s = m >> 5, b = m & 31;
            int w = words[b * S + s];
            ((float4*)g_X0)[idx] = ((const float4*)(emb + (long long)w * E))[c4];
        }
    }
}

// ---------------------------------------------------------------------------
// Tiled fp32 GEMM: C[m][n] = sum_k A[m][k]*Bm[k][n] + bias[n]
// BM=128, BN=64, BK=16, 256 threads, 8x4 micro-tile.
// layer 0: A=g_X0 (K=300), Bm=g_Wt0, C=g_GI0
// layer 1: A=g_H0 (K=400), Bm=g_Wt1, C=g_GI1
// ---------------------------------------------------------------------------
__global__ void gemm128(const float* __restrict__ bias, int K, int layer) {
    const float* A  = layer ? g_H0  : g_X0;
    const float* Bm = layer ? g_Wt1 : g_Wt0;
    float* C        = layer ? g_GI1 : g_GI0;
    __shared__ float As[16][128];
    __shared__ float Bs[16][64];
    const int tid = threadIdx.x;
    const int m0 = blockIdx.y * 128, n0 = blockIdx.x * 64;
    const int tx = tid & 15, ty = tid >> 4;
    float acc[8][4] = {};

    for (int k0 = 0; k0 < K; k0 += 16) {
        // As: 128 rows x 16 cols = 512 float4; each thread loads 2
#pragma unroll
        for (int i = 0; i < 2; i++) {
            int idx = tid + i * 256;          // 0..511
            int r = idx >> 2, c4 = idx & 3;   // r 0..127, c4 0..3
            int kk = k0 + c4 * 4;
            float4 v;
            if (kk + 3 < K) {
                v = *(const float4*)&A[(m0 + r) * K + kk];
            } else {
                float t0 = (kk + 0 < K) ? A[(m0 + r) * K + kk + 0] : 0.0f;
                float t1 = (kk + 1 < K) ? A[(m0 + r) * K + kk + 1] : 0.0f;
                float t2 = (kk + 2 < K) ? A[(m0 + r) * K + kk + 2] : 0.0f;
                float t3 = (kk + 3 < K) ? A[(m0 + r) * K + kk + 3] : 0.0f;
                v = make_float4(t0, t1, t2, t3);
            }
            As[c4 * 4 + 0][r] = v.x;
            As[c4 * 4 + 1][r] = v.y;
            As[c4 * 4 + 2][r] = v.z;
            As[c4 * 4 + 3][r] = v.w;
        }
        // Bs: 16 rows x 64 cols = 256 float4; each thread loads 1
        {
            int r = tid >> 4, c4 = tid & 15;
            int kk = k0 + r;
            float4 v = make_float4(0.f, 0.f, 0.f, 0.f);
            if (kk < K) v = *(const float4*)&Bm[kk * NT + n0 + c4 * 4];
            *(float4*)&Bs[r][c4 * 4] = v;
        }
        __syncthreads();
#pragma unroll
        for (int kk = 0; kk < 16; kk++) {
            float4 a0 = *(const float4*)&As[kk][ty * 8];
            float4 a1 = *(const float4*)&As[kk][ty * 8 + 4];
            float4 bv = *(const float4*)&Bs[kk][tx * 4];
            float aa[8] = {a0.x, a0.y, a0.z, a0.w, a1.x, a1.y, a1.z, a1.w};
            float bb[4] = {bv.x, bv.y, bv.z, bv.w};
#pragma unroll
            for (int i = 0; i < 8; i++)
#pragma unroll
                for (int j = 0; j < 4; j++)
                    acc[i][j] = fmaf(aa[i], bb[j], acc[i][j]);
        }
        __syncthreads();
    }
    float4 bv = *(const float4*)&bias[n0 + tx * 4];
#pragma unroll
    for (int i = 0; i < 8; i++) {
        int m = m0 + ty * 8 + i;
        float4 o;
        o.x = acc[i][0] + bv.x;
        o.y = acc[i][1] + bv.y;
        o.z = acc[i][2] + bv.z;
        o.w = acc[i][3] + bv.w;
        *(float4*)&C[m * NT + n0 + tx * 4] = o;
    }
}

// ---------------------------------------------------------------------------
// LSTM recurrence. Block = (pair of batches, direction). Threads 0..199 each
// own one hidden unit (c in register). h ping-pong in SMEM (1 barrier/step),
// U via coalesced LDG.128 (repacked), next-step GI prefetched.
// ---------------------------------------------------------------------------
__global__ void lstm_rec(int layer) {
    const float* GI  = layer ? g_GI1 : g_GI0;
    const float* UT4 = layer ? g_UT1 : g_UT0;
    float* Hout      = layer ? g_H1  : g_H0;
    const int bp = blockIdx.x;   // 0..15
    const int d = blockIdx.y;    // 0,1
    const int tid = threadIdx.x; // 0..223
    __shared__ float hs[2][2][200];   // [ping][batch01][j]
    float c0 = 0.0f, c1 = 0.0f;
    if (tid < 200) { hs[0][0][tid] = 0.0f; hs[0][1][tid] = 0.0f; }
    __syncthreads();
    const float* UTd = UT4 + d * 50 * (G * 4);
    const int b0 = bp * 2, b1 = b0 + 1;
    int p = 0;

    float ai0 = 0, af0 = 0, ag0 = 0, ao0 = 0, ai1 = 0, af1 = 0, ag1 = 0, ao1 = 0;
    // preload GI for step 0
    if (tid < 200) {
        const int t0i = d ? 127 : 0;
        const float* gi0 = GI + (t0i * B + b0) * NT + d * 800;
        const float* gi1 = gi0 + NT;
        ai0 = gi0[tid];       af0 = gi0[200 + tid];
        ag0 = gi0[400 + tid]; ao0 = gi0[600 + tid];
        ai1 = gi1[tid];       af1 = gi1[200 + tid];
        ag1 = gi1[400 + tid]; ao1 = gi1[600 + tid];
    }

    for (int step = 0; step < 128; step++) {
        const int t = d ? (127 - step) : step;
        if (tid < 200) {
            const float* h0p = hs[p][0];
            const float* h1p = hs[p][1];
#pragma unroll 2
            for (int kq = 0; kq < 50; kq++) {
                const float4* u = (const float4*)(UTd + kq * (G * 4));
                float4 ui = u[tid];
                float4 uf = u[200 + tid];
                float4 ug = u[400 + tid];
                float4 uo = u[600 + tid];
                float4 h0 = *(const float4*)&h0p[kq * 4];
                float4 h1 = *(const float4*)&h1p[kq * 4];
                ai0 = fmaf(h0.x, ui.x, ai0); ai0 = fmaf(h0.y, ui.y, ai0);
                ai0 = fmaf(h0.z, ui.z, ai0); ai0 = fmaf(h0.w, ui.w, ai0);
                af0 = fmaf(h0.x, uf.x, af0); af0 = fmaf(h0.y, uf.y, af0);
                af0 = fmaf(h0.z, uf.z, af0); af0 = fmaf(h0.w, uf.w, af0);
                ag0 = fmaf(h0.x, ug.x, ag0); ag0 = fmaf(h0.y, ug.y, ag0);
                ag0 = fmaf(h0.z, ug.z, ag0); ag0 = fmaf(h0.w, ug.w, ag0);
                ao0 = fmaf(h0.x, uo.x, ao0); ao0 = fmaf(h0.y, uo.y, ao0);
                ao0 = fmaf(h0.z, uo.z, ao0); ao0 = fmaf(h0.w, uo.w, ao0);
                ai1 = fmaf(h1.x, ui.x, ai1); ai1 = fmaf(h1.y, ui.y, ai1);
                ai1 = fmaf(h1.z, ui.z, ai1); ai1 = fmaf(h1.w, ui.w, ai1);
                af1 = fmaf(h1.x, uf.x, af1); af1 = fmaf(h1.y, uf.y, af1);
                af1 = fmaf(h1.z, uf.z, af1); af1 = fmaf(h1.w, uf.w, af1);
                ag1 = fmaf(h1.x, ug.x, ag1); ag1 = fmaf(h1.y, ug.y, ag1);
                ag1 = fmaf(h1.z, ug.z, ag1); ag1 = fmaf(h1.w, ug.w, ag1);
                ao1 = fmaf(h1.x, uo.x, ao1); ao1 = fmaf(h1.y, uo.y, ao1);
                ao1 = fmaf(h1.z, uo.z, ao1); ao1 = fmaf(h1.w, uo.w, ao1);
            }
            float cn0 = sigf(af0) * c0 + sigf(ai0) * tanhf(ag0);
            c0 = cn0;
            float hn0 = sigf(ao0) * tanhf(cn0);
            float cn1 = sigf(af1) * c1 + sigf(ai1) * tanhf(ag1);
            c1 = cn1;
            float hn1 = sigf(ao1) * tanhf(cn1);
            hs[p ^ 1][0][tid] = hn0;
            hs[p ^ 1][1][tid] = hn1;
            Hout[(t * B + b0) * 400 + d * 200 + tid] = hn0;
            Hout[(t * B + b1) * 400 + d * 200 + tid] = hn1;
            // prefetch next step's GI (overlaps barrier + next loop head)
            if (step < 127) {
                const int tn = d ? (126 - step) : (step + 1);
                const float* gi0 = GI + (tn * B + b0) * NT + d * 800;
                const float* gi1 = gi0 + NT;
                ai0 = gi0[tid];       af0 = gi0[200 + tid];
                ag0 = gi0[400 + tid]; ao0 = gi0[600 + tid];
                ai1 = gi1[tid];       af1 = gi1[200 + tid];
                ag1 = gi1[400 + tid]; ao1 = gi1[600 + tid];
            }
        }
        __syncthreads(); // publish hs[p^1]; also guards hs[p] overwrite next step
        p ^= 1;
    }
}

// ---------------------------------------------------------------------------
// Output projection: out[b][s][t] = sigmoid(g_H1[s][b][:400] . out_w[t] + out_b[t])
// ---------------------------------------------------------------------------
__global__ void out_proj(const float* __restrict__ ow,
                         const float* __restrict__ ob, float* __restrict__ out) {
    __shared__ float x[400];
    const int m = blockIdx.x; // s*B + b
    const int tid = threadIdx.x;
    for (int i = tid; i < 400; i += blockDim.x) x[i] = g_H1[m * 400 + i];
    __syncthreads();
    if (tid < 136) {
        const int tt = tid >> 3, l = tid & 7;
        float acc = 0.0f;
        for (int k = l; k < 400; k += 8) acc = fmaf(x[k], ow[tt * 400 + k], acc);
        unsigned mask = (tid < 128) ? 0xffffffffu : 0xffu;
        acc += __shfl_down_sync(mask, acc, 4, 8);
        acc += __shfl_down_sync(mask, acc, 2, 8);
        acc += __shfl_down_sync(mask, acc, 1, 8);
        if (l == 0) {
            int s = m >> 5, b = m & 31;
            out[(b * S + s) * T + tt] = sigf(acc + ob[tt]);
        }
    }
}

// ---------------------------------------------------------------------------
extern "C" void kernel_launch(void* const* d_in, const int* in_sizes, int n_in,
                              void* d_out, int out_size) {
    const int* words = (const int*)d_in[0];
    const float* emb = (const float*)d_in[3];
    const float* Wih0 = (const float*)d_in[7];
    const float* Whh0 = (const float*)d_in[8];
    const float* b0 = (const float*)d_in[9];
    const float* Wih1 = (const float*)d_in[10];
    const float* Whh1 = (const float*)d_in[11];
    const float* b1 = (const float*)d_in[12];
    const float* ow = (const float*)d_in[13];
    const float* ob = (const float*)d_in[14];
    float* out = (float*)d_out;

    // fused prep (transposes, U repack, embedding gather) — 1 launch
    prep<<<dim3(2500, 5), 256>>>(Wih0, Wih1, Whh0, Whh1, words, emb);
    // layer 0 input projection
    gemm128<<<dim3(NT / 64, MROWS / 128), 256>>>(b0, 300, 0);
    // layer 0 recurrence
    lstm_rec<<<dim3(16, 2), 224>>>(0);
    // layer 1 input projection
    gemm128<<<dim3(NT / 64, MROWS / 128), 256>>>(b1, 400, 1);
    // layer 1 recurrence
    lstm_rec<<<dim3(16, 2), 224>>>(1);
    // output projection
    out_proj<<<MROWS, 160>>>(ow, ob, out);
}

// round 5
// speedup vs baseline: 6.4120x; 6.2943x over previous
#include <cuda_runtime.h>
#include <cuda_bf16.h>
#include <math.h>
#include <stdint.h>

// Problem constants
#define S 128
#define B 32
#define E 300
#define H 200
#define G 800      // 4*H
#define NT 1600    // 2 dirs * G
#define MROWS 4096 // S*B
#define T 17

// Scratch (device globals; no allocation allowed)
__device__ float g_Wt0[300 * NT];          // W0^T  [k][d*800+g]
__device__ float g_Wt1[400 * NT];          // W1^T
__device__ float g_X0[MROWS * E];          // gathered embeddings [s*B+b][300]
__device__ float g_GI0[MROWS * NT];        // gate inputs layer0 [s][b][d*800+g]
__device__ float g_GI1[MROWS * NT];
__device__ float g_H0[MROWS * 400];        // layer0 output [s][b][400]
__device__ float g_H1[MROWS * 400];

__device__ __forceinline__ float sigf(float x) { return 1.0f / (1.0f + expf(-x)); }

__device__ __forceinline__ uint32_t smem_u32(const void* p) {
    uint32_t a;
    asm("{ .reg .u64 t; cvta.to.shared.u64 t, %1; cvt.u32.u64 %0, t; }" : "=r"(a) : "l"(p));
    return a;
}
__device__ __forceinline__ void st_cluster_f32(uint32_t laddr, uint32_t rank, float v) {
    uint32_t ra;
    asm volatile("mapa.shared::cluster.u32 %0, %1, %2;" : "=r"(ra) : "r"(laddr), "r"(rank));
    asm volatile("st.shared::cluster.f32 [%0], %1;" :: "r"(ra), "f"(v) : "memory");
}
#define CLUSTER_SYNC_() do { \
    asm volatile("barrier.cluster.arrive.aligned;" ::: "memory"); \
    asm volatile("barrier.cluster.wait.aligned;" ::: "memory"); \
} while (0)

// ---------------------------------------------------------------------------
// Fused prep: task 0: Wih0 -> g_Wt0; task 1: Wih1 -> g_Wt1; task 2: emb gather
// ---------------------------------------------------------------------------
__global__ void prep(const float* __restrict__ Wih0, const float* __restrict__ Wih1,
                     const int* __restrict__ words, const float* __restrict__ emb) {
    const int task = blockIdx.y;
    const int idx = blockIdx.x * 256 + threadIdx.x;
    if (task == 0) {
        if (idx < NT * 300) {
            int n = idx / 300, k = idx - n * 300;
            g_Wt0[k * NT + n] = Wih0[idx];
        }
    } else if (task == 1) {
        if (idx < NT * 400) {
            int n = idx / 400, k = idx - n * 400;
            g_Wt1[k * NT + n] = Wih1[idx];
        }
    } else {
        if (idx < MROWS * 75) {
            int m = idx / 75, c4 = idx - m * 75;
            int s = m >> 5, b = m & 31;
            int w = words[b * S + s];
            ((float4*)g_X0)[idx] = ((const float4*)(emb + (long long)w * E))[c4];
        }
    }
}

// ---------------------------------------------------------------------------
// Tiled fp32 GEMM: C[m][n] = sum_k A[m][k]*Bm[k][n] + bias[n]
// BM=128, BN=64, BK=16, 256 threads, 8x4 micro-tile.
// ---------------------------------------------------------------------------
__global__ void gemm128(const float* __restrict__ bias, int K, int layer) {
    const float* A  = layer ? g_H0  : g_X0;
    const float* Bm = layer ? g_Wt1 : g_Wt0;
    float* C        = layer ? g_GI1 : g_GI0;
    __shared__ float As[16][128];
    __shared__ float Bs[16][64];
    const int tid = threadIdx.x;
    const int m0 = blockIdx.y * 128, n0 = blockIdx.x * 64;
    const int tx = tid & 15, ty = tid >> 4;
    float acc[8][4] = {};

    for (int k0 = 0; k0 < K; k0 += 16) {
#pragma unroll
        for (int i = 0; i < 2; i++) {
            int idx = tid + i * 256;
            int r = idx >> 2, c4 = idx & 3;
            int kk = k0 + c4 * 4;
            float4 v;
            if (kk + 3 < K) {
                v = *(const float4*)&A[(m0 + r) * K + kk];
            } else {
                float t0 = (kk + 0 < K) ? A[(m0 + r) * K + kk + 0] : 0.0f;
                float t1 = (kk + 1 < K) ? A[(m0 + r) * K + kk + 1] : 0.0f;
                float t2 = (kk + 2 < K) ? A[(m0 + r) * K + kk + 2] : 0.0f;
                float t3 = (kk + 3 < K) ? A[(m0 + r) * K + kk + 3] : 0.0f;
                v = make_float4(t0, t1, t2, t3);
            }
            As[c4 * 4 + 0][r] = v.x;
            As[c4 * 4 + 1][r] = v.y;
            As[c4 * 4 + 2][r] = v.z;
            As[c4 * 4 + 3][r] = v.w;
        }
        {
            int r = tid >> 4, c4 = tid & 15;
            int kk = k0 + r;
            float4 v = make_float4(0.f, 0.f, 0.f, 0.f);
            if (kk < K) v = *(const float4*)&Bm[kk * NT + n0 + c4 * 4];
            *(float4*)&Bs[r][c4 * 4] = v;
        }
        __syncthreads();
#pragma unroll
        for (int kk = 0; kk < 16; kk++) {
            float4 a0 = *(const float4*)&As[kk][ty * 8];
            float4 a1 = *(const float4*)&As[kk][ty * 8 + 4];
            float4 bv = *(const float4*)&Bs[kk][tx * 4];
            float aa[8] = {a0.x, a0.y, a0.z, a0.w, a1.x, a1.y, a1.z, a1.w};
            float bb[4] = {bv.x, bv.y, bv.z, bv.w};
#pragma unroll
            for (int i = 0; i < 8; i++)
#pragma unroll
                for (int j = 0; j < 4; j++)
                    acc[i][j] = fmaf(aa[i], bb[j], acc[i][j]);
        }
        __syncthreads();
    }
    float4 bv = *(const float4*)&bias[n0 + tx * 4];
#pragma unroll
    for (int i = 0; i < 8; i++) {
        int m = m0 + ty * 8 + i;
        float4 o;
        o.x = acc[i][0] + bv.x;
        o.y = acc[i][1] + bv.y;
        o.z = acc[i][2] + bv.z;
        o.w = acc[i][3] + bv.w;
        *(float4*)&C[m * NT + n0 + tx * 4] = o;
    }
}

// ---------------------------------------------------------------------------
// Cluster-resident LSTM recurrence.
// Cluster of 4 CTAs per (batch-pair, direction). Each CTA owns a 50-wide slice
// of the hidden dim: U rows {gate 0..3} x {j in [crank*50, crank*50+50)},
// k=0..99 in registers (25 float4/thread), k=100..199 in SMEM.
// Per step: phase A (200 threads, one (gate,j) each, 2 batches) computes gate
// pre-acts from full h (local SMEM); phase B (100 threads, one (j,b) each)
// updates c, computes h, broadcasts h to all 4 CTAs via st.shared::cluster.
// One cluster barrier per step; h double-buffered.
// ---------------------------------------------------------------------------
__global__ void __cluster_dims__(4, 1, 1) __launch_bounds__(224, 1)
lstm_rec(const float* __restrict__ Whh, int layer) {
    const float* GI = layer ? g_GI1 : g_GI0;
    float* Hout     = layer ? g_H1  : g_H0;
    extern __shared__ float smem[];
    float* Usm  = smem;            // [25][200][4] = 20000 floats (k=100..199 half)
    float* hbuf = smem + 20000;    // [2][2][200]  = 800 floats
    float* ag   = smem + 20800;    // [4][50][2]   = 400 floats

    const int tid = threadIdx.x;     // 0..223
    uint32_t crank;
    asm("mov.u32 %0, %%cluster_ctarank;" : "=r"(crank));
    const int bg = blockIdx.y >> 1;  // batch pair 0..15
    const int d  = blockIdx.y & 1;   // direction
    const int bb0 = bg * 2, bb1 = bg * 2 + 1;

    const int gate = (tid < 200) ? (tid / 50) : 0;
    const int jl   = (tid < 200) ? (tid % 50) : 0;
    const int jglob = crank * 50 + jl;

    const float* WhhD = Whh + (size_t)d * (G * H);

    // --- init: load U (register half k<100 directly from global; SMEM half) ---
    float4 ureg[25];
    if (tid < 200) {
        const float* Urow = WhhD + (size_t)(gate * 200 + jglob) * 200;
#pragma unroll
        for (int kq = 0; kq < 25; kq++)
            ureg[kq] = *(const float4*)(Urow + kq * 4);
    }
    for (int idx = tid; idx < 5000; idx += 224) {
        int kq2 = idx / 200, t2 = idx % 200;
        int g2 = t2 / 50, j2 = t2 % 50;
        const float* r = WhhD + (size_t)(g2 * 200 + (int)crank * 50 + j2) * 200 + (25 + kq2) * 4;
        ((float4*)Usm)[idx] = *(const float4*)r;
    }
    for (int idx = tid; idx < 800; idx += 224) hbuf[idx] = 0.0f;
    __syncthreads();
    CLUSTER_SYNC_();   // peers' hbuf zeroed before any remote h store

    const uint32_t hb_u32 = smem_u32(hbuf);
    const float4* Usm4 = (const float4*)Usm;
    float cst = 0.0f;  // cell state for thread's (j,b) (threads 0..99)
    int p = 0;

    for (int step = 0; step < 128; step++) {
        const int tstep = d ? (127 - step) : step;
        // ---- phase A: gate pre-activations ----
        if (tid < 200) {
            const float* gbase = GI + (size_t)(tstep * B + bb0) * NT + d * 800 + gate * 200 + jglob;
            float gi0 = gbase[0];
            float gi1 = gbase[NT];
            float d0[2] = {0.f, 0.f}, d1[2] = {0.f, 0.f};
            const float4* hp0 = (const float4*)(hbuf + (p * 2 + 0) * 200);
            const float4* hp1 = (const float4*)(hbuf + (p * 2 + 1) * 200);
#pragma unroll
            for (int kq = 0; kq < 25; kq++) {
                float4 u = ureg[kq];
                float4 h0 = hp0[kq], h1 = hp1[kq];
                int a = kq & 1;
                d0[a] = fmaf(u.x, h0.x, d0[a]); d0[a] = fmaf(u.y, h0.y, d0[a]);
                d0[a] = fmaf(u.z, h0.z, d0[a]); d0[a] = fmaf(u.w, h0.w, d0[a]);
                d1[a] = fmaf(u.x, h1.x, d1[a]); d1[a] = fmaf(u.y, h1.y, d1[a]);
                d1[a] = fmaf(u.z, h1.z, d1[a]); d1[a] = fmaf(u.w, h1.w, d1[a]);
            }
#pragma unroll
            for (int kq = 0; kq < 25; kq++) {
                float4 u = Usm4[kq * 200 + tid];
                float4 h0 = hp0[25 + kq], h1 = hp1[25 + kq];
                int a = kq & 1;
                d0[a] = fmaf(u.x, h0.x, d0[a]); d0[a] = fmaf(u.y, h0.y, d0[a]);
                d0[a] = fmaf(u.z, h0.z, d0[a]); d0[a] = fmaf(u.w, h0.w, d0[a]);
                d1[a] = fmaf(u.x, h1.x, d1[a]); d1[a] = fmaf(u.y, h1.y, d1[a]);
                d1[a] = fmaf(u.z, h1.z, d1[a]); d1[a] = fmaf(u.w, h1.w, d1[a]);
            }
            ag[gate * 100 + jl * 2 + 0] = d0[0] + d0[1] + gi0;
            ag[gate * 100 + jl * 2 + 1] = d1[0] + d1[1] + gi1;
        }
        __syncthreads();
        // ---- phase B: cell update + cluster h broadcast ----
        if (tid < 100) {
            float aI = ag[tid], aF = ag[100 + tid], aG = ag[200 + tid], aO = ag[300 + tid];
            cst = sigf(aF) * cst + sigf(aI) * tanhf(aG);
            float hv = sigf(aO) * tanhf(cst);
            const int b = tid & 1, jlc = tid >> 1;
            const int jg = (int)crank * 50 + jlc;
            const int pn = p ^ 1;
            uint32_t ha = hb_u32 + (uint32_t)(((pn * 2 + b) * 200 + jg) * 4);
            st_cluster_f32(ha, 0, hv);
            st_cluster_f32(ha, 1, hv);
            st_cluster_f32(ha, 2, hv);
            st_cluster_f32(ha, 3, hv);
            Hout[(size_t)(tstep * B + bg * 2 + b) * 400 + d * 200 + jg] = hv;
        }
        CLUSTER_SYNC_();  // h published everywhere; also fences ag reuse
        p ^= 1;
    }
}

// ---------------------------------------------------------------------------
// Output projection: out[b][s][t] = sigmoid(g_H1[s][b][:400] . out_w[t] + out_b[t])
// ---------------------------------------------------------------------------
__global__ void out_proj(const float* __restrict__ ow,
                         const float* __restrict__ ob, float* __restrict__ out) {
    __shared__ float x[400];
    const int m = blockIdx.x; // s*B + b
    const int tid = threadIdx.x;
    for (int i = tid; i < 400; i += blockDim.x) x[i] = g_H1[m * 400 + i];
    __syncthreads();
    if (tid < 136) {
        const int tt = tid >> 3, l = tid & 7;
        float acc = 0.0f;
        for (int k = l; k < 400; k += 8) acc = fmaf(x[k], ow[tt * 400 + k], acc);
        unsigned mask = (tid < 128) ? 0xffffffffu : 0xffu;
        acc += __shfl_down_sync(mask, acc, 4, 8);
        acc += __shfl_down_sync(mask, acc, 2, 8);
        acc += __shfl_down_sync(mask, acc, 1, 8);
        if (l == 0) {
            int s = m >> 5, b = m & 31;
            out[(b * S + s) * T + tt] = sigf(acc + ob[tt]);
        }
    }
}

// ---------------------------------------------------------------------------
extern "C" void kernel_launch(void* const* d_in, const int* in_sizes, int n_in,
                              void* d_out, int out_size) {
    const int* words = (const int*)d_in[0];
    const float* emb = (const float*)d_in[3];
    const float* Wih0 = (const float*)d_in[7];
    const float* Whh0 = (const float*)d_in[8];
    const float* b0 = (const float*)d_in[9];
    const float* Wih1 = (const float*)d_in[10];
    const float* Whh1 = (const float*)d_in[11];
    const float* b1 = (const float*)d_in[12];
    const float* ow = (const float*)d_in[13];
    const float* ob = (const float*)d_in[14];
    float* out = (float*)d_out;

    const int LSTM_SMEM = (20000 + 800 + 400) * 4; // 84800 B
    static int attr_done = 0;
    if (!attr_done) {
        cudaFuncSetAttribute(lstm_rec, cudaFuncAttributeMaxDynamicSharedMemorySize, LSTM_SMEM);
        attr_done = 1;
    }

    // prep: W transposes + embedding gather
    prep<<<dim3(2500, 3), 256>>>(Wih0, Wih1, words, emb);
    // layer 0 input projection
    gemm128<<<dim3(NT / 64, MROWS / 128), 256>>>(b0, 300, 0);
    // layer 0 recurrence (32 clusters of 4 CTAs)
    lstm_rec<<<dim3(4, 32), 224, LSTM_SMEM>>>(Whh0, 0);
    // layer 1 input projection
    gemm128<<<dim3(NT / 64, MROWS / 128), 256>>>(b1, 400, 1);
    // layer 1 recurrence
    lstm_rec<<<dim3(4, 32), 224, LSTM_SMEM>>>(Whh1, 1);
    // output projection
    out_proj<<<MROWS, 160>>>(ow, ob, out);
}

// round 7
// speedup vs baseline: 7.7314x; 1.2058x over previous
#include <cuda_runtime.h>
#include <cuda_bf16.h>
#include <math.h>
#include <stdint.h>

// Problem constants
#define S 128
#define B 32
#define E 300
#define H 200
#define G 800      // 4*H
#define NT 1600    // 2 dirs * G
#define MROWS 4096 // S*B
#define T 17

// Scratch (device globals; no allocation allowed)
__device__ float g_Wt0[300 * NT];          // W0^T  [k][d*800+g]
__device__ float g_Wt1[400 * NT];          // W1^T
__device__ float g_X0[MROWS * E];          // gathered embeddings [s*B+b][300]
__device__ float g_GI0[MROWS * NT];        // gate inputs layer0 [s][b][d*800+g]
__device__ float g_GI1[MROWS * NT];
__device__ float g_H0[MROWS * 400];        // layer0 output [s][b][400]
__device__ float g_H1[MROWS * 400];

__device__ __forceinline__ float sigf(float x) { return 1.0f / (1.0f + expf(-x)); }

__device__ __forceinline__ uint32_t smem_u32(const void* p) {
    uint32_t a;
    asm("{ .reg .u64 t; cvta.to.shared.u64 t, %1; cvt.u32.u64 %0, t; }" : "=r"(a) : "l"(p));
    return a;
}
__device__ __forceinline__ void st_cluster_f32(uint32_t laddr, uint32_t rank, float v) {
    uint32_t ra;
    asm volatile("mapa.shared::cluster.u32 %0, %1, %2;" : "=r"(ra) : "r"(laddr), "r"(rank));
    asm volatile("st.shared::cluster.f32 [%0], %1;" :: "r"(ra), "f"(v) : "memory");
}
__device__ __forceinline__ uint32_t f2tf32(float f) {
    uint32_t u;
    asm("cvt.rna.tf32.f32 %0, %1;" : "=r"(u) : "f"(f));
    return u;
}
__device__ __forceinline__ void mma_tf32(float* c, const uint32_t* a, const uint32_t* b) {
    asm volatile(
        "mma.sync.aligned.m16n8k8.row.col.f32.tf32.tf32.f32 "
        "{%0,%1,%2,%3}, {%4,%5,%6,%7}, {%8,%9}, {%0,%1,%2,%3};"
        : "+f"(c[0]), "+f"(c[1]), "+f"(c[2]), "+f"(c[3])
        : "r"(a[0]), "r"(a[1]), "r"(a[2]), "r"(a[3]), "r"(b[0]), "r"(b[1]));
}

// ---------------------------------------------------------------------------
// Fused prep: task 0: Wih0 -> g_Wt0; task 1: Wih1 -> g_Wt1; task 2: emb gather
// ---------------------------------------------------------------------------
__global__ void prep(const float* __restrict__ Wih0, const float* __restrict__ Wih1,
                     const int* __restrict__ words, const float* __restrict__ emb) {
    const int task = blockIdx.y;
    const int idx = blockIdx.x * 256 + threadIdx.x;
    if (task == 0) {
        if (idx < NT * 300) {
            int n = idx / 300, k = idx - n * 300;
            g_Wt0[k * NT + n] = Wih0[idx];
        }
    } else if (task == 1) {
        if (idx < NT * 400) {
            int n = idx / 400, k = idx - n * 400;
            g_Wt1[k * NT + n] = Wih1[idx];
        }
    } else {
        if (idx < MROWS * 75) {
            int m = idx / 75, c4 = idx - m * 75;
            int s = m >> 5, b = m & 31;
            int w = words[b * S + s];
            ((float4*)g_X0)[idx] = ((const float4*)(emb + (long long)w * E))[c4];
        }
    }
}

// ---------------------------------------------------------------------------
// tf32 tensor-core GEMM: C[m][n] = sum_k A[m][k]*Bm[k][n] + bias[n]
// BM=128, BN=64, BK=16, 256 threads (8 warps, 4x2), warp tile 32x32,
// mma.m16n8k8.tf32, double-buffered SMEM, cvt.rna at SMEM-store time.
// As: [128][20] (m-major, pad->conflict-free frag loads)
// Bs: [16][72]  (k-major, pad 64->72)
// ---------------------------------------------------------------------------
#define ASZ (128 * 20)
#define BSZ (16 * 72)
__global__ void __launch_bounds__(256) gemm_tc(const float* __restrict__ bias,
                                               int K, int layer) {
    const float* A  = layer ? g_H0  : g_X0;
    const float* Bm = layer ? g_Wt1 : g_Wt0;
    float* C        = layer ? g_GI1 : g_GI0;
    __shared__ uint32_t sm[2][ASZ + BSZ];

    const int tid = threadIdx.x;
    const int lane = tid & 31, wid = tid >> 5;
    const int g = lane >> 2, tg = lane & 3;
    const int warp_m = (wid & 3) * 32;    // 0,32,64,96
    const int warp_n = (wid >> 2) * 32;   // 0,32
    const int m0 = blockIdx.y * 128, n0 = blockIdx.x * 64;

    float acc[2][4][4] = {};
    const int ntiles = (K + 15) / 16;

    const int br = tid >> 4, bc4 = tid & 15;       // B: 1 float4 per thread

    float4 la[2], lb;
    // prefetch tile 0
    {
        const int k0 = 0;
#pragma unroll
        for (int i = 0; i < 2; i++) {
            int idx = tid + i * 256;
            int r = idx >> 2, c4 = idx & 3;
            int kk = k0 + c4 * 4;
            float4 v = make_float4(0.f, 0.f, 0.f, 0.f);
            if (kk + 3 < K) v = *(const float4*)&A[(m0 + r) * K + kk];
            else {
                if (kk + 0 < K) v.x = A[(m0 + r) * K + kk + 0];
                if (kk + 1 < K) v.y = A[(m0 + r) * K + kk + 1];
                if (kk + 2 < K) v.z = A[(m0 + r) * K + kk + 2];
                if (kk + 3 < K) v.w = A[(m0 + r) * K + kk + 3];
            }
            la[i] = v;
        }
        {
            int kk = k0 + br;
            lb = make_float4(0.f, 0.f, 0.f, 0.f);
            if (kk < K) lb = *(const float4*)&Bm[kk * NT + n0 + bc4 * 4];
        }
    }
    // store tile 0
#pragma unroll
    for (int i = 0; i < 2; i++) {
        int idx = tid + i * 256;
        int r = idx >> 2, c4 = idx & 3;
        uint4 u = make_uint4(f2tf32(la[i].x), f2tf32(la[i].y), f2tf32(la[i].z), f2tf32(la[i].w));
        *(uint4*)&sm[0][r * 20 + c4 * 4] = u;
    }
    {
        uint4 u = make_uint4(f2tf32(lb.x), f2tf32(lb.y), f2tf32(lb.z), f2tf32(lb.w));
        *(uint4*)&sm[0][ASZ + br * 72 + bc4 * 4] = u;
    }
    __syncthreads();

    int cur = 0;
    for (int t = 0; t < ntiles; t++) {
        // prefetch next tile into regs
        if (t + 1 < ntiles) {
            const int k0 = (t + 1) * 16;
#pragma unroll
            for (int i = 0; i < 2; i++) {
                int idx = tid + i * 256;
                int r = idx >> 2, c4 = idx & 3;
                int kk = k0 + c4 * 4;
                float4 v = make_float4(0.f, 0.f, 0.f, 0.f);
                if (kk + 3 < K) v = *(const float4*)&A[(m0 + r) * K + kk];
                else {
                    if (kk + 0 < K) v.x = A[(m0 + r) * K + kk + 0];
                    if (kk + 1 < K) v.y = A[(m0 + r) * K + kk + 1];
                    if (kk + 2 < K) v.z = A[(m0 + r) * K + kk + 2];
                    if (kk + 3 < K) v.w = A[(m0 + r) * K + kk + 3];
                }
                la[i] = v;
            }
            int kk = k0 + br;
            lb = make_float4(0.f, 0.f, 0.f, 0.f);
            if (kk < K) lb = *(const float4*)&Bm[kk * NT + n0 + bc4 * 4];
        }
        // compute on sm[cur]
        const uint32_t* As = sm[cur];
        const uint32_t* Bs = sm[cur] + ASZ;
#pragma unroll
        for (int k8 = 0; k8 < 16; k8 += 8) {
            uint32_t a[2][4], b[4][2];
#pragma unroll
            for (int mi = 0; mi < 2; mi++) {
                int row = warp_m + mi * 16;
                a[mi][0] = As[(row + g) * 20 + k8 + tg];
                a[mi][1] = As[(row + g + 8) * 20 + k8 + tg];
                a[mi][2] = As[(row + g) * 20 + k8 + tg + 4];
                a[mi][3] = As[(row + g + 8) * 20 + k8 + tg + 4];
            }
#pragma unroll
            for (int ni = 0; ni < 4; ni++) {
                int col = warp_n + ni * 8 + g;
                b[ni][0] = Bs[(k8 + tg) * 72 + col];
                b[ni][1] = Bs[(k8 + tg + 4) * 72 + col];
            }
#pragma unroll
            for (int mi = 0; mi < 2; mi++)
#pragma unroll
                for (int ni = 0; ni < 4; ni++)
                    mma_tf32(acc[mi][ni], a[mi], b[ni]);
        }
        // store next tile to alternate buffer
        if (t + 1 < ntiles) {
            uint32_t* d = sm[cur ^ 1];
#pragma unroll
            for (int i = 0; i < 2; i++) {
                int idx = tid + i * 256;
                int r = idx >> 2, c4 = idx & 3;
                uint4 u = make_uint4(f2tf32(la[i].x), f2tf32(la[i].y), f2tf32(la[i].z), f2tf32(la[i].w));
                *(uint4*)&d[r * 20 + c4 * 4] = u;
            }
            uint4 u = make_uint4(f2tf32(lb.x), f2tf32(lb.y), f2tf32(lb.z), f2tf32(lb.w));
            *(uint4*)&d[ASZ + br * 72 + bc4 * 4] = u;
        }
        __syncthreads();
        cur ^= 1;
    }

    // epilogue: add bias, store (float2 per c-pair)
#pragma unroll
    for (int mi = 0; mi < 2; mi++) {
        int r0 = m0 + warp_m + mi * 16 + g;
        int r1 = r0 + 8;
#pragma unroll
        for (int ni = 0; ni < 4; ni++) {
            int c = n0 + warp_n + ni * 8 + tg * 2;
            float2 bv = *(const float2*)&bias[c];
            float2 o0, o1;
            o0.x = acc[mi][ni][0] + bv.x; o0.y = acc[mi][ni][1] + bv.y;
            o1.x = acc[mi][ni][2] + bv.x; o1.y = acc[mi][ni][3] + bv.y;
            *(float2*)&C[(size_t)r0 * NT + c] = o0;
            *(float2*)&C[(size_t)r1 * NT + c] = o1;
        }
    }
}

// ---------------------------------------------------------------------------
// Cluster-resident LSTM recurrence (4-CTA cluster per batch-pair x direction).
// Split cluster arrive/wait with GI prefetch between them.
// ---------------------------------------------------------------------------
__global__ void __cluster_dims__(4, 1, 1) __launch_bounds__(224, 1)
lstm_rec(const float* __restrict__ Whh, int layer) {
    const float* GI = layer ? g_GI1 : g_GI0;
    float* Hout     = layer ? g_H1  : g_H0;
    extern __shared__ float smem[];
    float* Usm  = smem;            // [25][200][4] = 20000 floats (k=100..199 half)
    float* hbuf = smem + 20000;    // [2][2][200]
    float* ag   = smem + 20800;    // [4][50][2]

    const int tid = threadIdx.x;     // 0..223
    uint32_t crank;
    asm("mov.u32 %0, %%cluster_ctarank;" : "=r"(crank));
    const int bg = blockIdx.y >> 1;
    const int d  = blockIdx.y & 1;
    const int bb0 = bg * 2;

    const int gate = (tid < 200) ? (tid / 50) : 0;
    const int jl   = (tid < 200) ? (tid % 50) : 0;
    const int jglob = crank * 50 + jl;

    const float* WhhD = Whh + (size_t)d * (G * H);

    float4 ureg[25];
    if (tid < 200) {
        const float* Urow = WhhD + (size_t)(gate * 200 + jglob) * 200;
#pragma unroll
        for (int kq = 0; kq < 25; kq++)
            ureg[kq] = *(const float4*)(Urow + kq * 4);
    }
    for (int idx = tid; idx < 5000; idx += 224) {
        int kq2 = idx / 200, t2 = idx % 200;
        int g2 = t2 / 50, j2 = t2 % 50;
        const float* r = WhhD + (size_t)(g2 * 200 + (int)crank * 50 + j2) * 200 + (25 + kq2) * 4;
        ((float4*)Usm)[idx] = *(const float4*)r;
    }
    for (int idx = tid; idx < 800; idx += 224) hbuf[idx] = 0.0f;
    __syncthreads();
    asm volatile("barrier.cluster.arrive.aligned;" ::: "memory");
    asm volatile("barrier.cluster.wait.aligned;" ::: "memory");

    const uint32_t hb_u32 = smem_u32(hbuf);
    const float4* Usm4 = (const float4*)(const void*)Usm;
    float cst = 0.0f;
    int p = 0;

    // preload GI for step 0
    float gi0 = 0.f, gi1 = 0.f;
    if (tid < 200) {
        const int t0i = d ? 127 : 0;
        const float* gb = GI + (size_t)(t0i * B + bb0) * NT + d * 800 + gate * 200 + jglob;
        gi0 = gb[0];
        gi1 = gb[NT];
    }

    for (int step = 0; step < 128; step++) {
        const int tstep = d ? (127 - step) : step;
        // ---- phase A: gate pre-activations ----
        if (tid < 200) {
            float d0[2] = {0.f, 0.f}, d1[2] = {0.f, 0.f};
            const float4* hp0 = (const float4*)(const void*)(hbuf + (p * 2 + 0) * 200);
            const float4* hp1 = (const float4*)(const void*)(hbuf + (p * 2 + 1) * 200);
#pragma unroll
            for (int kq = 0; kq < 25; kq++) {
                float4 u = ureg[kq];
                float4 h0 = hp0[kq], h1 = hp1[kq];
                int a = kq & 1;
                d0[a] = fmaf(u.x, h0.x, d0[a]); d0[a] = fmaf(u.y, h0.y, d0[a]);
                d0[a] = fmaf(u.z, h0.z, d0[a]); d0[a] = fmaf(u.w, h0.w, d0[a]);
                d1[a] = fmaf(u.x, h1.x, d1[a]); d1[a] = fmaf(u.y, h1.y, d1[a]);
                d1[a] = fmaf(u.z, h1.z, d1[a]); d1[a] = fmaf(u.w, h1.w, d1[a]);
            }
#pragma unroll
            for (int kq = 0; kq < 25; kq++) {
                float4 u = Usm4[kq * 200 + tid];
                float4 h0 = hp0[25 + kq], h1 = hp1[25 + kq];
                int a = kq & 1;
                d0[a] = fmaf(u.x, h0.x, d0[a]); d0[a] = fmaf(u.y, h0.y, d0[a]);
                d0[a] = fmaf(u.z, h0.z, d0[a]); d0[a] = fmaf(u.w, h0.w, d0[a]);
                d1[a] = fmaf(u.x, h1.x, d1[a]); d1[a] = fmaf(u.y, h1.y, d1[a]);
                d1[a] = fmaf(u.z, h1.z, d1[a]); d1[a] = fmaf(u.w, h1.w, d1[a]);
            }
            ag[gate * 100 + jl * 2 + 0] = d0[0] + d0[1] + gi0;
            ag[gate * 100 + jl * 2 + 1] = d1[0] + d1[1] + gi1;
        }
        __syncthreads();
        // ---- phase B: cell update + cluster h broadcast ----
        if (tid < 100) {
            float aI = ag[tid], aF = ag[100 + tid], aG = ag[200 + tid], aO = ag[300 + tid];
            cst = sigf(aF) * cst + sigf(aI) * tanhf(aG);
            float hv = sigf(aO) * tanhf(cst);
            const int b = tid & 1, jlc = tid >> 1;
            const int jg = (int)crank * 50 + jlc;
            const int pn = p ^ 1;
            uint32_t ha = hb_u32 + (uint32_t)(((pn * 2 + b) * 200 + jg) * 4);
            st_cluster_f32(ha, 0, hv);
            st_cluster_f32(ha, 1, hv);
            st_cluster_f32(ha, 2, hv);
            st_cluster_f32(ha, 3, hv);
            Hout[(size_t)(tstep * B + bg * 2 + b) * 400 + d * 200 + jg] = hv;
        }
        asm volatile("barrier.cluster.arrive.aligned;" ::: "memory");
        // prefetch next step's GI while peers finish (hidden under cluster skew)
        if (step < 127 && tid < 200) {
            const int tn = d ? (126 - step) : (step + 1);
            const float* gb = GI + (size_t)(tn * B + bb0) * NT + d * 800 + gate * 200 + jglob;
            gi0 = gb[0];
            gi1 = gb[NT];
        }
        asm volatile("barrier.cluster.wait.aligned;" ::: "memory");
        p ^= 1;
    }
}

// ---------------------------------------------------------------------------
// Output projection
// ---------------------------------------------------------------------------
__global__ void out_proj(const float* __restrict__ ow,
                         const float* __restrict__ ob, float* __restrict__ out) {
    __shared__ float x[400];
    const int m = blockIdx.x; // s*B + b
    const int tid = threadIdx.x;
    for (int i = tid; i < 400; i += blockDim.x) x[i] = g_H1[m * 400 + i];
    __syncthreads();
    if (tid < 136) {
        const int tt = tid >> 3, l = tid & 7;
        float acc = 0.0f;
        for (int k = l; k < 400; k += 8) acc = fmaf(x[k], ow[tt * 400 + k], acc);
        unsigned mask = (tid < 128) ? 0xffffffffu : 0xffu;
        acc += __shfl_down_sync(mask, acc, 4, 8);
        acc += __shfl_down_sync(mask, acc, 2, 8);
        acc += __shfl_down_sync(mask, acc, 1, 8);
        if (l == 0) {
            int s = m >> 5, b = m & 31;
            out[(b * S + s) * T + tt] = sigf(acc + ob[tt]);
        }
    }
}

// ---------------------------------------------------------------------------
extern "C" void kernel_launch(void* const* d_in, const int* in_sizes, int n_in,
                              void* d_out, int out_size) {
    const int* words = (const int*)d_in[0];
    const float* emb = (const float*)d_in[3];
    const float* Wih0 = (const float*)d_in[7];
    const float* Whh0 = (const float*)d_in[8];
    const float* b0 = (const float*)d_in[9];
    const float* Wih1 = (const float*)d_in[10];
    const float* Whh1 = (const float*)d_in[11];
    const float* b1 = (const float*)d_in[12];
    const float* ow = (const float*)d_in[13];
    const float* ob = (const float*)d_in[14];
    float* out = (float*)d_out;

    const int LSTM_SMEM = (20000 + 800 + 400) * 4; // 84800 B
    // unconditional (no static guards) — cheap host-side call, capture-safe
    cudaFuncSetAttribute(lstm_rec, cudaFuncAttributeMaxDynamicSharedMemorySize, LSTM_SMEM);

    // prep: W transposes + embedding gather
    prep<<<dim3(2500, 3), 256>>>(Wih0, Wih1, words, emb);
    // layer 0 input projection (tf32 TC)
    gemm_tc<<<dim3(NT / 64, MROWS / 128), 256>>>(b0, 300, 0);
    // layer 0 recurrence (32 clusters of 4 CTAs)
    lstm_rec<<<dim3(4, 32), 224, LSTM_SMEM>>>(Whh0, 0);
    // layer 1 input projection (tf32 TC)
    gemm_tc<<<dim3(NT / 64, MROWS / 128), 256>>>(b1, 400, 1);
    // layer 1 recurrence
    lstm_rec<<<dim3(4, 32), 224, LSTM_SMEM>>>(Whh1, 1);
    // output projection
    out_proj<<<MROWS, 160>>>(ow, ob, out);
}

// round 8
// speedup vs baseline: 8.9999x; 1.1641x over previous
#include <cuda_runtime.h>
#include <cuda_bf16.h>
#include <math.h>
#include <stdint.h>

// Problem constants
#define S 128
#define B 32
#define E 300
#define H 200
#define G 800      // 4*H
#define NT 1600    // 2 dirs * G
#define MROWS 4096 // S*B
#define T 17

// Scratch (device globals). Wt*/X0/H0 hold tf32-converted bit patterns
// (stored as float bit-casts); GI*/H1 are true fp32.
__device__ float g_Wt0[300 * NT];          // W0^T  [k][d*800+g]  (tf32 bits)
__device__ float g_Wt1[400 * NT];          // W1^T               (tf32 bits)
__device__ float g_X0[MROWS * E];          // gathered embeddings (tf32 bits)
__device__ float g_GI0[MROWS * NT];        // gate inputs layer0 (fp32)
__device__ float g_GI1[MROWS * NT];
__device__ float g_H0[MROWS * 400];        // layer0 output (tf32 bits)
__device__ float g_H1[MROWS * 400];        // layer1 output (fp32)

__device__ __forceinline__ float sigf(float x) { return 1.0f / (1.0f + expf(-x)); }

__device__ __forceinline__ uint32_t smem_u32(const void* p) {
    uint32_t a;
    asm("{ .reg .u64 t; cvta.to.shared.u64 t, %1; cvt.u32.u64 %0, t; }" : "=r"(a) : "l"(p));
    return a;
}
__device__ __forceinline__ void st_cluster_f32(uint32_t laddr, uint32_t rank, float v) {
    uint32_t ra;
    asm volatile("mapa.shared::cluster.u32 %0, %1, %2;" : "=r"(ra) : "r"(laddr), "r"(rank));
    asm volatile("st.shared::cluster.f32 [%0], %1;" :: "r"(ra), "f"(v) : "memory");
}
#define CLUSTER_SYNC_() do { \
    asm volatile("barrier.cluster.arrive.aligned;" ::: "memory"); \
    asm volatile("barrier.cluster.wait.aligned;" ::: "memory"); \
} while (0)

__device__ __forceinline__ uint32_t f2tf32(float f) {
    uint32_t u;
    asm("cvt.rna.tf32.f32 %0, %1;" : "=r"(u) : "f"(f));
    return u;
}
// packed dual-fp32 FMA (Blackwell FFMA2; PTX-only form)
__device__ __forceinline__ uint64_t fma2(uint64_t a, uint64_t b, uint64_t c) {
    uint64_t d;
    asm("fma.rn.f32x2 %0, %1, %2, %3;" : "=l"(d) : "l"(a), "l"(b), "l"(c));
    return d;
}
__device__ __forceinline__ float2 unpack2(uint64_t v) {
    uint32_t lo, hi;
    asm("mov.b64 {%0,%1}, %2;" : "=r"(lo), "=r"(hi) : "l"(v));
    return make_float2(__uint_as_float(lo), __uint_as_float(hi));
}
__device__ __forceinline__ void mma_tf32(float* c, const uint32_t* a, const uint32_t* b) {
    asm volatile(
        "mma.sync.aligned.m16n8k8.row.col.f32.tf32.tf32.f32 "
        "{%0,%1,%2,%3}, {%4,%5,%6,%7}, {%8,%9}, {%0,%1,%2,%3};"
        : "+f"(c[0]), "+f"(c[1]), "+f"(c[2]), "+f"(c[3])
        : "r"(a[0]), "r"(a[1]), "r"(a[2]), "r"(a[3]), "r"(b[0]), "r"(b[1]));
}

// ---------------------------------------------------------------------------
// Fused prep (all outputs pre-converted to tf32 bits):
//  task 0: Wih0 -> g_Wt0 ; task 1: Wih1 -> g_Wt1 ; task 2: emb gather -> g_X0
// ---------------------------------------------------------------------------
__global__ void prep(const float* __restrict__ Wih0, const float* __restrict__ Wih1,
                     const int* __restrict__ words, const float* __restrict__ emb) {
    const int task = blockIdx.y;
    const int idx = blockIdx.x * 256 + threadIdx.x;
    if (task == 0) {
        if (idx < NT * 300) {
            int n = idx / 300, k = idx - n * 300;
            g_Wt0[k * NT + n] = __uint_as_float(f2tf32(Wih0[idx]));
        }
    } else if (task == 1) {
        if (idx < NT * 400) {
            int n = idx / 400, k = idx - n * 400;
            g_Wt1[k * NT + n] = __uint_as_float(f2tf32(Wih1[idx]));
        }
    } else {
        if (idx < MROWS * 75) {
            int m = idx / 75, c4 = idx - m * 75;
            int s = m >> 5, b = m & 31;
            int w = words[b * S + s];
            float4 v = ((const float4*)(emb + (long long)w * E))[c4];
            float4 o;
            o.x = __uint_as_float(f2tf32(v.x));
            o.y = __uint_as_float(f2tf32(v.y));
            o.z = __uint_as_float(f2tf32(v.z));
            o.w = __uint_as_float(f2tf32(v.w));
            ((float4*)g_X0)[idx] = o;
        }
    }
}

// ---------------------------------------------------------------------------
// tf32 tensor-core GEMM (operands pre-converted): C = A*Bm + bias
// BM=128, BN=64, BK=16, 256 threads (8 warps, 4x2), warp tile 32x32,
// mma.m16n8k8.tf32, double-buffered SMEM.
// As: [128][20] pad; Bs: [16][72] pad.
// ---------------------------------------------------------------------------
#define ASZ (128 * 20)
#define BSZ (16 * 72)
__global__ void __launch_bounds__(256) gemm_tc(const float* __restrict__ bias,
                                               int K, int layer) {
    const uint32_t* A  = (const uint32_t*)(layer ? g_H0  : g_X0);
    const uint32_t* Bm = (const uint32_t*)(layer ? g_Wt1 : g_Wt0);
    float* C           = layer ? g_GI1 : g_GI0;
    __shared__ uint32_t sm[2][ASZ + BSZ];

    const int tid = threadIdx.x;
    const int lane = tid & 31, wid = tid >> 5;
    const int g = lane >> 2, tg = lane & 3;
    const int warp_m = (wid & 3) * 32;
    const int warp_n = (wid >> 2) * 32;
    const int m0 = blockIdx.y * 128, n0 = blockIdx.x * 64;

    float acc[2][4][4] = {};
    const int ntiles = (K + 15) / 16;
    const int br = tid >> 4, bc4 = tid & 15;

    uint4 la[2], lb;
    // prefetch tile 0
#pragma unroll
    for (int i = 0; i < 2; i++) {
        int idx = tid + i * 256;
        int r = idx >> 2, c4 = idx & 3;
        int kk = c4 * 4;
        uint4 v = make_uint4(0u, 0u, 0u, 0u);
        if (kk + 3 < K) v = *(const uint4*)&A[(m0 + r) * K + kk];
        else {
            if (kk + 0 < K) v.x = A[(m0 + r) * K + kk + 0];
            if (kk + 1 < K) v.y = A[(m0 + r) * K + kk + 1];
            if (kk + 2 < K) v.z = A[(m0 + r) * K + kk + 2];
            if (kk + 3 < K) v.w = A[(m0 + r) * K + kk + 3];
        }
        la[i] = v;
    }
    {
        lb = make_uint4(0u, 0u, 0u, 0u);
        if (br < K) lb = *(const uint4*)&Bm[br * NT + n0 + bc4 * 4];
    }
#pragma unroll
    for (int i = 0; i < 2; i++) {
        int idx = tid + i * 256;
        int r = idx >> 2, c4 = idx & 3;
        *(uint4*)&sm[0][r * 20 + c4 * 4] = la[i];
    }
    *(uint4*)&sm[0][ASZ + br * 72 + bc4 * 4] = lb;
    __syncthreads();

    int cur = 0;
    for (int t = 0; t < ntiles; t++) {
        if (t + 1 < ntiles) {
            const int k0 = (t + 1) * 16;
#pragma unroll
            for (int i = 0; i < 2; i++) {
                int idx = tid + i * 256;
                int r = idx >> 2, c4 = idx & 3;
                int kk = k0 + c4 * 4;
                uint4 v = make_uint4(0u, 0u, 0u, 0u);
                if (kk + 3 < K) v = *(const uint4*)&A[(m0 + r) * K + kk];
                else {
                    if (kk + 0 < K) v.x = A[(m0 + r) * K + kk + 0];
                    if (kk + 1 < K) v.y = A[(m0 + r) * K + kk + 1];
                    if (kk + 2 < K) v.z = A[(m0 + r) * K + kk + 2];
                    if (kk + 3 < K) v.w = A[(m0 + r) * K + kk + 3];
                }
                la[i] = v;
            }
            int kk = k0 + br;
            lb = make_uint4(0u, 0u, 0u, 0u);
            if (kk < K) lb = *(const uint4*)&Bm[kk * NT + n0 + bc4 * 4];
        }
        const uint32_t* As = sm[cur];
        const uint32_t* Bs = sm[cur] + ASZ;
#pragma unroll
        for (int k8 = 0; k8 < 16; k8 += 8) {
            uint32_t a[2][4], b[4][2];
#pragma unroll
            for (int mi = 0; mi < 2; mi++) {
                int row = warp_m + mi * 16;
                a[mi][0] = As[(row + g) * 20 + k8 + tg];
                a[mi][1] = As[(row + g + 8) * 20 + k8 + tg];
                a[mi][2] = As[(row + g) * 20 + k8 + tg + 4];
                a[mi][3] = As[(row + g + 8) * 20 + k8 + tg + 4];
            }
#pragma unroll
            for (int ni = 0; ni < 4; ni++) {
                int col = warp_n + ni * 8 + g;
                b[ni][0] = Bs[(k8 + tg) * 72 + col];
                b[ni][1] = Bs[(k8 + tg + 4) * 72 + col];
            }
#pragma unroll
            for (int mi = 0; mi < 2; mi++)
#pragma unroll
                for (int ni = 0; ni < 4; ni++)
                    mma_tf32(acc[mi][ni], a[mi], b[ni]);
        }
        if (t + 1 < ntiles) {
            uint32_t* d = sm[cur ^ 1];
#pragma unroll
            for (int i = 0; i < 2; i++) {
                int idx = tid + i * 256;
                int r = idx >> 2, c4 = idx & 3;
                *(uint4*)&d[r * 20 + c4 * 4] = la[i];
            }
            *(uint4*)&d[ASZ + br * 72 + bc4 * 4] = lb;
        }
        __syncthreads();
        cur ^= 1;
    }

#pragma unroll
    for (int mi = 0; mi < 2; mi++) {
        int r0 = m0 + warp_m + mi * 16 + g;
        int r1 = r0 + 8;
#pragma unroll
        for (int ni = 0; ni < 4; ni++) {
            int c = n0 + warp_n + ni * 8 + tg * 2;
            float2 bv = *(const float2*)&bias[c];
            float2 o0, o1;
            o0.x = acc[mi][ni][0] + bv.x; o0.y = acc[mi][ni][1] + bv.y;
            o1.x = acc[mi][ni][2] + bv.x; o1.y = acc[mi][ni][3] + bv.y;
            *(float2*)&C[(size_t)r0 * NT + c] = o0;
            *(float2*)&C[(size_t)r1 * NT + c] = o1;
        }
    }
}

// ---------------------------------------------------------------------------
// Cluster-resident LSTM recurrence, f32x2 edition.
// 4-CTA cluster per (batch-pair, direction); each CTA owns 50 hidden units.
// ALL of this CTA's U slice lives in registers as packed k-pairs (100 uint64).
// h broadcast from SMEM as ulonglong2 (2 k-pairs per 16B load). Packed FMA
// vectorizes over k; 4 independent accumulator chains.
// layer 0 stores Hout pre-converted to tf32 bits (consumed by gemm L1).
// ---------------------------------------------------------------------------
__global__ void __cluster_dims__(4, 1, 1) __launch_bounds__(224, 1)
lstm_rec(const float* __restrict__ Whh, int layer) {
    const float* GI = layer ? g_GI1 : g_GI0;
    float* Hout     = layer ? g_H1  : g_H0;
    __shared__ float hbuf[2 * 2 * 200];  // [ping][batch01][j]
    __shared__ float ag[400];            // [gate][j][batch01]

    const int tid = threadIdx.x;     // 0..223
    uint32_t crank;
    asm("mov.u32 %0, %%cluster_ctarank;" : "=r"(crank));
    const int bg = blockIdx.y >> 1;
    const int d  = blockIdx.y & 1;
    const int bb0 = bg * 2;

    const int gate = (tid < 200) ? (tid / 50) : 0;
    const int jl   = (tid < 200) ? (tid % 50) : 0;
    const int jglob = crank * 50 + jl;

    const float* WhhD = Whh + (size_t)d * (G * H);

    // whole U row (200 floats) in registers as 100 packed k-pairs
    uint64_t upair[100];
    if (tid < 200) {
        const ulonglong2* Urow =
            (const ulonglong2*)(WhhD + (size_t)(gate * 200 + jglob) * 200);
#pragma unroll
        for (int kq = 0; kq < 50; kq++) {
            ulonglong2 t = Urow[kq];
            upair[2 * kq] = t.x;
            upair[2 * kq + 1] = t.y;
        }
    }
    for (int idx = tid; idx < 800; idx += 224) hbuf[idx] = 0.0f;
    __syncthreads();
    CLUSTER_SYNC_();   // peers' hbuf zeroed before any remote h store

    const uint32_t hb_u32 = smem_u32(hbuf);
    float cst = 0.0f;
    int p = 0;

    for (int step = 0; step < 128; step++) {
        const int tstep = d ? (127 - step) : step;
        // ---- phase A: gate pre-activations ----
        if (tid < 200) {
            // GI loads issue now, consumed only at the end -> latency hidden
            const float* gb = GI + (size_t)(tstep * B + bb0) * NT + d * 800
                              + gate * 200 + jglob;
            float gi0 = gb[0];
            float gi1 = gb[NT];
            const ulonglong2* hp0 = (const ulonglong2*)(hbuf + (p * 2 + 0) * 200);
            const ulonglong2* hp1 = (const ulonglong2*)(hbuf + (p * 2 + 1) * 200);
            uint64_t a00 = 0, a01 = 0, a10 = 0, a11 = 0;
#pragma unroll
            for (int kq = 0; kq < 50; kq++) {
                ulonglong2 h0 = hp0[kq];
                ulonglong2 h1 = hp1[kq];
                a00 = fma2(upair[2 * kq],     h0.x, a00);
                a01 = fma2(upair[2 * kq + 1], h0.y, a01);
                a10 = fma2(upair[2 * kq],     h1.x, a10);
                a11 = fma2(upair[2 * kq + 1], h1.y, a11);
            }
            float2 s00 = unpack2(a00), s01 = unpack2(a01);
            float2 s10 = unpack2(a10), s11 = unpack2(a11);
            ag[gate * 100 + jl * 2 + 0] = (s00.x + s00.y) + (s01.x + s01.y) + gi0;
            ag[gate * 100 + jl * 2 + 1] = (s10.x + s10.y) + (s11.x + s11.y) + gi1;
        }
        __syncthreads();
        // ---- phase B: cell update + cluster h broadcast ----
        if (tid < 100) {
            float aI = ag[tid], aF = ag[100 + tid], aG = ag[200 + tid], aO = ag[300 + tid];
            cst = sigf(aF) * cst + sigf(aI) * tanhf(aG);
            float hv = sigf(aO) * tanhf(cst);
            const int b = tid & 1, jlc = tid >> 1;
            const int jg = (int)crank * 50 + jlc;
            const int pn = p ^ 1;
            uint32_t ha = hb_u32 + (uint32_t)(((pn * 2 + b) * 200 + jg) * 4);
            st_cluster_f32(ha, 0, hv);
            st_cluster_f32(ha, 1, hv);
            st_cluster_f32(ha, 2, hv);
            st_cluster_f32(ha, 3, hv);
            float hstore = layer ? hv : __uint_as_float(f2tf32(hv));
            Hout[(size_t)(tstep * B + bg * 2 + b) * 400 + d * 200 + jg] = hstore;
        }
        CLUSTER_SYNC_();  // h published everywhere; also fences ag reuse
        p ^= 1;
    }
}

// ---------------------------------------------------------------------------
// Output projection
// ---------------------------------------------------------------------------
__global__ void out_proj(const float* __restrict__ ow,
                         const float* __restrict__ ob, float* __restrict__ out) {
    __shared__ float x[400];
    const int m = blockIdx.x; // s*B + b
    const int tid = threadIdx.x;
    for (int i = tid; i < 400; i += blockDim.x) x[i] = g_H1[m * 400 + i];
    __syncthreads();
    if (tid < 136) {
        const int tt = tid >> 3, l = tid & 7;
        float acc = 0.0f;
        for (int k = l; k < 400; k += 8) acc = fmaf(x[k], ow[tt * 400 + k], acc);
        unsigned mask = (tid < 128) ? 0xffffffffu : 0xffu;
        acc += __shfl_down_sync(mask, acc, 4, 8);
        acc += __shfl_down_sync(mask, acc, 2, 8);
        acc += __shfl_down_sync(mask, acc, 1, 8);
        if (l == 0) {
            int s = m >> 5, b = m & 31;
            out[(b * S + s) * T + tt] = sigf(acc + ob[tt]);
        }
    }
}

// ---------------------------------------------------------------------------
extern "C" void kernel_launch(void* const* d_in, const int* in_sizes, int n_in,
                              void* d_out, int out_size) {
    const int* words = (const int*)d_in[0];
    const float* emb = (const float*)d_in[3];
    const float* Wih0 = (const float*)d_in[7];
    const float* Whh0 = (const float*)d_in[8];
    const float* b0 = (const float*)d_in[9];
    const float* Wih1 = (const float*)d_in[10];
    const float* Whh1 = (const float*)d_in[11];
    const float* b1 = (const float*)d_in[12];
    const float* ow = (const float*)d_in[13];
    const float* ob = (const float*)d_in[14];
    float* out = (float*)d_out;

    // prep: W transposes + embedding gather (tf32 pre-conversion)
    prep<<<dim3(2500, 3), 256>>>(Wih0, Wih1, words, emb);
    // layer 0 input projection (tf32 TC)
    gemm_tc<<<dim3(NT / 64, MROWS / 128), 256>>>(b0, 300, 0);
    // layer 0 recurrence (32 clusters of 4 CTAs)
    lstm_rec<<<dim3(4, 32), 224>>>(Whh0, 0);
    // layer 1 input projection (tf32 TC)
    gemm_tc<<<dim3(NT / 64, MROWS / 128), 256>>>(b1, 400, 1);
    // layer 1 recurrence
    lstm_rec<<<dim3(4, 32), 224>>>(Whh1, 1);
    // output projection
    out_proj<<<MROWS, 160>>>(ow, ob, out);
}